// round 3
// baseline (speedup 1.0000x reference)
#include <cuda_runtime.h>
#include <cstdint>

#define D          512
#define ROW_BYTES  2048
#define MARGIN     1.0f
#define NSTAGE     3
#define G          2                 // triplets per stage (one per warp)
#define TPB        64                // 2 warps
#define GRID       512
#define PER_BLOCK  32                // 512 * 32 = 16384 triplets
#define ITERS      (PER_BLOCK / G)   // 16
#define STAGE_BYTES (G * 3 * ROW_BYTES)

__global__ void zero_out_kernel(float* out) {
    if (threadIdx.x == 0) out[0] = 0.0f;
}

__device__ __forceinline__ uint32_t smem_u32(const void* p) {
    return (uint32_t)__cvta_generic_to_shared(p);
}

__device__ __forceinline__ void mbar_init(uint32_t addr, uint32_t count) {
    asm volatile("mbarrier.init.shared::cta.b64 [%0], %1;" :: "r"(addr), "r"(count) : "memory");
}
__device__ __forceinline__ void mbar_expect_tx(uint32_t addr, uint32_t bytes) {
    asm volatile("mbarrier.arrive.expect_tx.shared::cta.b64 _, [%0], %1;"
                 :: "r"(addr), "r"(bytes) : "memory");
}
__device__ __forceinline__ void mbar_arrive(uint32_t addr) {
    asm volatile("mbarrier.arrive.shared::cta.b64 _, [%0];" :: "r"(addr) : "memory");
}
__device__ __forceinline__ void mbar_wait(uint32_t addr, uint32_t parity) {
    uint32_t done = 0;
    while (!done) {
        asm volatile(
            "{\n\t.reg .pred p;\n\t"
            "mbarrier.try_wait.parity.shared::cta.b64 p, [%1], %2, 0x989680;\n\t"
            "selp.b32 %0, 1, 0, p;\n\t}"
            : "=r"(done) : "r"(addr), "r"(parity) : "memory");
    }
}
// Bulk async copy global -> shared (UBLKCP), completion via mbarrier tx bytes.
__device__ __forceinline__ void bulk_g2s(uint32_t dst_smem, const void* src_gmem,
                                         uint32_t bytes, uint32_t mbar) {
    asm volatile(
        "cp.async.bulk.shared::cluster.global.mbarrier::complete_tx::bytes "
        "[%0], [%1], %2, [%3];"
        :: "r"(dst_smem), "l"(src_gmem), "r"(bytes), "r"(mbar) : "memory");
}

__global__ void __launch_bounds__(TPB)
triplet_pipeline_kernel(const float* __restrict__ batch,
                        const int* __restrict__ triplets,
                        float* __restrict__ out) {
    __shared__ __align__(1024) float rows[NSTAGE][G][3][D];
    __shared__ __align__(8) unsigned long long full_bar[NSTAGE];
    __shared__ __align__(8) unsigned long long empty_bar[NSTAGE];
    __shared__ int   idx_s[PER_BLOCK * 3];
    __shared__ float warp_part[TPB / 32];

    const int tid  = threadIdx.x;
    const int lane = tid & 31;
    const int wid  = tid >> 5;

    // Stage indices for this block's 32 triplets (96 ints) -> smem, cooperatively.
    {
        const int base = blockIdx.x * PER_BLOCK * 3;
        for (int k = tid; k < PER_BLOCK * 3; k += TPB)
            idx_s[k] = triplets[base + k];
    }
    if (tid == 0) {
        #pragma unroll
        for (int s = 0; s < NSTAGE; s++) {
            mbar_init(smem_u32(&full_bar[s]),  1);  // expect_tx arrive
            mbar_init(smem_u32(&empty_bar[s]), 2);  // one arrive per warp
        }
        asm volatile("fence.proxy.async.shared::cta;" ::: "memory");
    }
    __syncthreads();

    // Prologue: fill all stages (fresh empty barriers -> no wait needed).
    if (tid == 0) {
        #pragma unroll
        for (int j = 0; j < NSTAGE; j++) {
            const uint32_t fb = smem_u32(&full_bar[j]);
            mbar_expect_tx(fb, STAGE_BYTES);
            #pragma unroll
            for (int g = 0; g < G; g++) {
                #pragma unroll
                for (int r = 0; r < 3; r++) {
                    const int idx = idx_s[(j * G + g) * 3 + r];
                    bulk_g2s(smem_u32(&rows[j][g][r][0]),
                             batch + (size_t)idx * D, ROW_BYTES, fb);
                }
            }
        }
    }

    float acc = 0.0f;  // lane0-of-warp accumulator

    for (int i = 0; i < ITERS; i++) {
        const int s  = i % NSTAGE;
        const int ph = (i / NSTAGE) & 1;

        mbar_wait(smem_u32(&full_bar[s]), ph);

        // Warp `wid` computes triplet slot (s, wid).
        const float4* A = reinterpret_cast<const float4*>(&rows[s][wid][0][0]);
        const float4* P = reinterpret_cast<const float4*>(&rows[s][wid][1][0]);
        const float4* N = reinterpret_cast<const float4*>(&rows[s][wid][2][0]);

        float d_ap = 0.0f, d_an = 0.0f;
        #pragma unroll
        for (int j = 0; j < 4; j++) {
            const int k = lane + j * 32;
            const float4 a = A[k];
            const float4 p = P[k];
            const float4 n = N[k];
            float dx;
            dx = a.x - p.x; d_ap = fmaf(dx, dx, d_ap);
            dx = a.y - p.y; d_ap = fmaf(dx, dx, d_ap);
            dx = a.z - p.z; d_ap = fmaf(dx, dx, d_ap);
            dx = a.w - p.w; d_ap = fmaf(dx, dx, d_ap);
            dx = a.x - n.x; d_an = fmaf(dx, dx, d_an);
            dx = a.y - n.y; d_an = fmaf(dx, dx, d_an);
            dx = a.z - n.z; d_an = fmaf(dx, dx, d_an);
            dx = a.w - n.w; d_an = fmaf(dx, dx, d_an);
        }
        #pragma unroll
        for (int off = 16; off > 0; off >>= 1) {
            d_ap += __shfl_down_sync(0xFFFFFFFFu, d_ap, off);
            d_an += __shfl_down_sync(0xFFFFFFFFu, d_an, off);
        }
        if (lane == 0) {
            const float loss = d_ap - d_an + MARGIN;
            acc += fmaxf(loss, 0.0f);
            mbar_arrive(smem_u32(&empty_bar[s]));
        }

        // Producer: refill stage s for iteration j = i + NSTAGE.
        const int j = i + NSTAGE;
        if (j < ITERS && tid == 0) {
            const uint32_t pph = ((uint32_t)(j / NSTAGE) & 1u) ^ 1u;
            mbar_wait(smem_u32(&empty_bar[s]), pph);
            const uint32_t fb = smem_u32(&full_bar[s]);
            mbar_expect_tx(fb, STAGE_BYTES);
            #pragma unroll
            for (int g = 0; g < G; g++) {
                #pragma unroll
                for (int r = 0; r < 3; r++) {
                    const int idx = idx_s[(j * G + g) * 3 + r];
                    bulk_g2s(smem_u32(&rows[s][g][r][0]),
                             batch + (size_t)idx * D, ROW_BYTES, fb);
                }
            }
        }
    }

    if (lane == 0) warp_part[wid] = acc;
    __syncthreads();
    if (tid == 0) {
        const float total = warp_part[0] + warp_part[1];
        atomicAdd(out, total);
    }
}

extern "C" void kernel_launch(void* const* d_in, const int* in_sizes, int n_in,
                              void* d_out, int out_size) {
    const float* batch    = (const float*)d_in[0];
    const int*   triplets = (const int*)d_in[1];
    float* out = (float*)d_out;

    zero_out_kernel<<<1, 32>>>(out);
    triplet_pipeline_kernel<<<GRID, TPB>>>(batch, triplets, out);
}

// round 4
// speedup vs baseline: 1.2980x; 1.2980x over previous
#include <cuda_runtime.h>
#include <cstdint>

#define D 512
#define MARGIN 1.0f
#define WARPS_PER_BLOCK 8
#define THREADS_PER_BLOCK (WARPS_PER_BLOCK * 32)

__global__ void zero_out_kernel(float* out) {
    if (threadIdx.x == 0 && blockIdx.x == 0) out[0] = 0.0f;
}

// Packed dual-FMA: acc.{lo,hi} += a.{lo,hi} * b.{lo,hi}  (one FFMA2 instruction)
__device__ __forceinline__ void fma2(unsigned long long& acc,
                                     unsigned long long a,
                                     unsigned long long b) {
    asm("fma.rn.f32x2 %0, %1, %2, %0;" : "+l"(acc) : "l"(a), "l"(b));
}

__device__ __forceinline__ float lo_f(unsigned long long v) {
    return __uint_as_float((unsigned)(v & 0xFFFFFFFFull));
}
__device__ __forceinline__ float hi_f(unsigned long long v) {
    return __uint_as_float((unsigned)(v >> 32));
}

__global__ void __launch_bounds__(THREADS_PER_BLOCK, 4)
triplet_loss_kernel(const float* __restrict__ batch,
                    const int* __restrict__ triplets,
                    float* __restrict__ out,
                    int bs) {
    __shared__ float block_sum;
    if (threadIdx.x == 0) block_sum = 0.0f;
    __syncthreads();

    const int lane = threadIdx.x & 31;
    const int warp_global = (blockIdx.x * blockDim.x + threadIdx.x) >> 5;

    if (warp_global < bs) {
        const int ia = triplets[warp_global * 3 + 0];
        const int ip = triplets[warp_global * 3 + 1];
        const int in = triplets[warp_global * 3 + 2];

        // Rows viewed as 16-byte ulonglong2: each 64-bit half is a packed f32 pair.
        const ulonglong2* __restrict__ A =
            reinterpret_cast<const ulonglong2*>(batch + (size_t)ia * D) + lane;
        const ulonglong2* __restrict__ P =
            reinterpret_cast<const ulonglong2*>(batch + (size_t)ip * D) + lane;
        const ulonglong2* __restrict__ N =
            reinterpret_cast<const ulonglong2*>(batch + (size_t)in * D) + lane;

        // d_ap - d_an = Sp - Sn - 2*Sap + 2*San   (Sum a^2 cancels)
        unsigned long long Sp = 0, Sn = 0, Sap = 0, San = 0;  // packed 0.0f pairs

        #pragma unroll
        for (int j = 0; j < 4; j++) {
            const ulonglong2 a = A[j * 32];
            const ulonglong2 p = P[j * 32];
            const ulonglong2 n = N[j * 32];

            fma2(Sp,  p.x, p.x);  fma2(Sp,  p.y, p.y);
            fma2(Sn,  n.x, n.x);  fma2(Sn,  n.y, n.y);
            fma2(Sap, a.x, p.x);  fma2(Sap, a.y, p.y);
            fma2(San, a.x, n.x);  fma2(San, a.y, n.y);
        }

        // Fold packed halves and combine into ONE scalar per lane.
        const float sp  = lo_f(Sp)  + hi_f(Sp);
        const float sn  = lo_f(Sn)  + hi_f(Sn);
        const float sap = lo_f(Sap) + hi_f(Sap);
        const float san = lo_f(San) + hi_f(San);
        float v = (sp - sn) + 2.0f * (san - sap);

        // Single-value warp reduction: 5 shuffles.
        #pragma unroll
        for (int off = 16; off > 0; off >>= 1)
            v += __shfl_down_sync(0xFFFFFFFFu, v, off);

        if (lane == 0) {
            const float loss = v + MARGIN;
            if (loss > 0.0f) atomicAdd(&block_sum, loss);
        }
    }

    __syncthreads();
    if (threadIdx.x == 0) {
        const float s = block_sum;
        if (s != 0.0f) atomicAdd(out, s);
    }
}

extern "C" void kernel_launch(void* const* d_in, const int* in_sizes, int n_in,
                              void* d_out, int out_size) {
    const float* batch    = (const float*)d_in[0];
    const int*   triplets = (const int*)d_in[1];
    float* out = (float*)d_out;

    const int bs = in_sizes[1] / 3;  // 16384 triplets

    zero_out_kernel<<<1, 32>>>(out);

    const int blocks = (bs + WARPS_PER_BLOCK - 1) / WARPS_PER_BLOCK;
    triplet_loss_kernel<<<blocks, THREADS_PER_BLOCK>>>(batch, triplets, out, bs);
}

// round 5
// speedup vs baseline: 1.3208x; 1.0175x over previous
#include <cuda_runtime.h>
#include <cstdint>

#define D          512
#define ROW_BYTES  2048
#define MARGIN     1.0f
#define NSTAGE     2
#define WPB        4                  // warps per block
#define TPB        (WPB * 32)
#define GRID       512
#define ITERS      8                  // triplets per warp: 512*4*8 = 16384
#define STAGE_TX   (3 * ROW_BYTES)    // 6144 bytes per triplet stage

__global__ void zero_out_kernel(float* out) {
    if (threadIdx.x == 0) out[0] = 0.0f;
}

__device__ __forceinline__ uint32_t smem_u32(const void* p) {
    return (uint32_t)__cvta_generic_to_shared(p);
}
__device__ __forceinline__ void mbar_init(uint32_t addr, uint32_t count) {
    asm volatile("mbarrier.init.shared::cta.b64 [%0], %1;" :: "r"(addr), "r"(count) : "memory");
}
__device__ __forceinline__ void mbar_expect_tx(uint32_t addr, uint32_t bytes) {
    asm volatile("mbarrier.arrive.expect_tx.shared::cta.b64 _, [%0], %1;"
                 :: "r"(addr), "r"(bytes) : "memory");
}
__device__ __forceinline__ void mbar_wait(uint32_t addr, uint32_t parity) {
    uint32_t done = 0;
    while (!done) {
        asm volatile(
            "{\n\t.reg .pred p;\n\t"
            "mbarrier.try_wait.parity.acquire.cta.shared::cta.b64 p, [%1], %2, 0x989680;\n\t"
            "selp.b32 %0, 1, 0, p;\n\t}"
            : "=r"(done) : "r"(addr), "r"(parity) : "memory");
    }
}
__device__ __forceinline__ void bulk_g2s(uint32_t dst_smem, const void* src_gmem,
                                         uint32_t bytes, uint32_t mbar) {
    asm volatile(
        "cp.async.bulk.shared::cluster.global.mbarrier::complete_tx::bytes "
        "[%0], [%1], %2, [%3];"
        :: "r"(dst_smem), "l"(src_gmem), "r"(bytes), "r"(mbar) : "memory");
}
__device__ __forceinline__ void fma2(unsigned long long& acc,
                                     unsigned long long a,
                                     unsigned long long b) {
    asm("fma.rn.f32x2 %0, %1, %2, %0;" : "+l"(acc) : "l"(a), "l"(b));
}
__device__ __forceinline__ float lo_f(unsigned long long v) {
    return __uint_as_float((unsigned)(v & 0xFFFFFFFFull));
}
__device__ __forceinline__ float hi_f(unsigned long long v) {
    return __uint_as_float((unsigned)(v >> 32));
}

__global__ void __launch_bounds__(TPB)
triplet_warp_pipe_kernel(const float* __restrict__ batch,
                         const int* __restrict__ triplets,
                         float* __restrict__ out) {
    // Dynamic smem: rows[WPB][NSTAGE][3][D] floats = 49152 bytes.
    extern __shared__ __align__(1024) float rows[];
    __shared__ __align__(8) unsigned long long full_bar[WPB][NSTAGE];
    __shared__ int   idx_s[WPB][ITERS * 3];
    __shared__ float warp_part[WPB];

    const int tid  = threadIdx.x;
    const int lane = tid & 31;
    const int wid  = tid >> 5;
    const int warp_global = blockIdx.x * WPB + wid;

    // This warp's 8 triplets (24 indices) -> smem.
    if (lane < ITERS * 3)
        idx_s[wid][lane] = triplets[warp_global * (ITERS * 3) + lane];

    if (tid < WPB * NSTAGE)
        mbar_init(smem_u32(&full_bar[tid >> 1][tid & 1]), 1);
    if (tid == 0)
        asm volatile("fence.proxy.async.shared::cta;" ::: "memory");
    __syncthreads();

    // Per-warp slot base (floats): warp wid, stage s, row r.
    #define SLOT(w, s, r) (rows + (((w) * NSTAGE + (s)) * 3 + (r)) * D)

    // Prologue: lane 0 of each warp fills both of its stages.
    if (lane == 0) {
        #pragma unroll
        for (int s = 0; s < NSTAGE; s++) {
            const uint32_t fb = smem_u32(&full_bar[wid][s]);
            mbar_expect_tx(fb, STAGE_TX);
            #pragma unroll
            for (int r = 0; r < 3; r++) {
                const int idx = idx_s[wid][s * 3 + r];
                bulk_g2s(smem_u32(SLOT(wid, s, r)),
                         batch + (size_t)idx * D, ROW_BYTES, fb);
            }
        }
    }

    float acc = 0.0f;  // lane-0 accumulator

    #pragma unroll 1
    for (int i = 0; i < ITERS; i++) {
        const int s  = i & 1;
        const int ph = (i >> 1) & 1;

        mbar_wait(smem_u32(&full_bar[wid][s]), ph);

        const ulonglong2* A = reinterpret_cast<const ulonglong2*>(SLOT(wid, s, 0)) + lane;
        const ulonglong2* P = reinterpret_cast<const ulonglong2*>(SLOT(wid, s, 1)) + lane;
        const ulonglong2* N = reinterpret_cast<const ulonglong2*>(SLOT(wid, s, 2)) + lane;

        // d_ap - d_an = Sp - Sn - 2*Sap + 2*San  (Sum a^2 cancels)
        unsigned long long Sp = 0, Sn = 0, Sap = 0, San = 0;
        #pragma unroll
        for (int j = 0; j < 4; j++) {
            const ulonglong2 a = A[j * 32];
            const ulonglong2 p = P[j * 32];
            const ulonglong2 n = N[j * 32];
            fma2(Sp,  p.x, p.x);  fma2(Sp,  p.y, p.y);
            fma2(Sn,  n.x, n.x);  fma2(Sn,  n.y, n.y);
            fma2(Sap, a.x, p.x);  fma2(Sap, a.y, p.y);
            fma2(San, a.x, n.x);  fma2(San, a.y, n.y);
        }
        float v = (lo_f(Sp) + hi_f(Sp)) - (lo_f(Sn) + hi_f(Sn))
                + 2.0f * ((lo_f(San) + hi_f(San)) - (lo_f(Sap) + hi_f(Sap)));

        #pragma unroll
        for (int off = 16; off > 0; off >>= 1)
            v += __shfl_down_sync(0xFFFFFFFFu, v, off);

        if (lane == 0) acc += fmaxf(v + MARGIN, 0.0f);

        // All lanes done reading stage s -> refill for triplet i+2.
        __syncwarp();
        const int j = i + NSTAGE;
        if (j < ITERS && lane == 0) {
            asm volatile("fence.proxy.async.shared::cta;" ::: "memory");
            const uint32_t fb = smem_u32(&full_bar[wid][s]);
            mbar_expect_tx(fb, STAGE_TX);
            #pragma unroll
            for (int r = 0; r < 3; r++) {
                const int idx = idx_s[wid][j * 3 + r];
                bulk_g2s(smem_u32(SLOT(wid, s, r)),
                         batch + (size_t)idx * D, ROW_BYTES, fb);
            }
        }
    }

    if (lane == 0) warp_part[wid] = acc;
    __syncthreads();
    if (tid == 0) {
        float total = 0.0f;
        #pragma unroll
        for (int w = 0; w < WPB; w++) total += warp_part[w];
        atomicAdd(out, total);
    }
    #undef SLOT
}

extern "C" void kernel_launch(void* const* d_in, const int* in_sizes, int n_in,
                              void* d_out, int out_size) {
    const float* batch    = (const float*)d_in[0];
    const int*   triplets = (const int*)d_in[1];
    float* out = (float*)d_out;

    const int smem_bytes = WPB * NSTAGE * 3 * D * sizeof(float);  // 49152
    static bool attr_set = false;
    if (!attr_set) {
        cudaFuncSetAttribute(triplet_warp_pipe_kernel,
                             cudaFuncAttributeMaxDynamicSharedMemorySize, smem_bytes);
        attr_set = true;
    }

    zero_out_kernel<<<1, 32>>>(out);
    triplet_warp_pipe_kernel<<<GRID, TPB, smem_bytes>>>(batch, triplets, out);
}